// round 1
// baseline (speedup 1.0000x reference)
#include <cuda_runtime.h>
#include <cuda_bf16.h>
#include <cstdint>

// ---------------------------------------------------------------------------
// SimpleGCN: 3-layer GCN (PyG GCNConv semantics) on B200.
//   per layer: h = in @ W ; out[i] = sum_{e: dst==i} h[src_e]*dinv[src]*dinv[dst]
//              + h[i]*dinv[i]^2 (self loop) + b ; leaky_relu between layers.
// Strategy: fused GEMM+selfloop+bias kernel, edge scatter with red.global.v4.f32.
// ---------------------------------------------------------------------------

#define MAXN (1 << 17)   // >= 100000 nodes
#define FDIM 64

__device__ float g_h[(size_t)MAXN * FDIM];    // per-layer transformed features
__device__ float g_acc[(size_t)MAXN * FDIM];  // per-layer accumulator
__device__ float g_dinv[MAXN];                // deg -> d^{-1/2} (in place)
__device__ int   g_is64;                      // 1 if edge_index is int64

// --- dtype detection: int64 little-endian with values < 2^32 has zero odd words
__global__ void k_detect(const unsigned int* __restrict__ w, long long nwords) {
    __shared__ int cnt;
    if (threadIdx.x == 0) cnt = 0;
    __syncthreads();
    int zeros = 0;
    for (long long i = threadIdx.x; i < 2048 && i < nwords; i += blockDim.x)
        if ((i & 1) && w[i] == 0u) zeros++;
    atomicAdd(&cnt, zeros);
    __syncthreads();
    if (threadIdx.x == 0) g_is64 = (cnt > 512) ? 1 : 0;
}

__device__ __forceinline__ int load_idx(const void* e, long long pos) {
    if (g_is64) return (int)((const long long*)e)[pos];
    return ((const int*)e)[pos];
}

// --- degree: deg[i] = 1 (self loop) + #edges with dst==i
__global__ void k_initdeg(int n) {
    int i = blockIdx.x * blockDim.x + threadIdx.x;
    if (i < n) g_dinv[i] = 1.0f;
}

__global__ void k_deg(const void* __restrict__ e, long long E) {
    long long i = (long long)blockIdx.x * blockDim.x + threadIdx.x;
    if (i >= E) return;
    int d = load_idx(e, E + i);   // row 1 = dst
    atomicAdd(&g_dinv[d], 1.0f);
}

__global__ void k_dinv(int n) {
    int i = blockIdx.x * blockDim.x + threadIdx.x;
    if (i < n) g_dinv[i] = rsqrtf(g_dinv[i]);   // deg >= 1 always
}

// --- fused: h = act(in) @ W ; acc[i] = h[i]*dinv[i]^2 + b
// One thread per node row. W staged in shared (16 KB), broadcast reads.
// Safe in place (in == acc): thread r reads only row r, then writes row r.
template <int LRELU>
__global__ void __launch_bounds__(128)
k_gemm_init(const float* __restrict__ in, const float* __restrict__ W,
            const float* __restrict__ b, float* __restrict__ h,
            float* __restrict__ acc, int n) {
    __shared__ float Ws[FDIM * FDIM];
    __shared__ float bs[FDIM];
    for (int i = threadIdx.x; i < FDIM * FDIM; i += blockDim.x) Ws[i] = W[i];
    if (threadIdx.x < FDIM) bs[threadIdx.x] = b[threadIdx.x];
    __syncthreads();

    int r = blockIdx.x * blockDim.x + threadIdx.x;
    if (r >= n) return;

    float a[FDIM];
#pragma unroll
    for (int j = 0; j < FDIM; j++) a[j] = 0.0f;

    const float4* x4 = (const float4*)(in + (size_t)r * FDIM);
#pragma unroll 4
    for (int k4 = 0; k4 < FDIM / 4; k4++) {
        float4 xv = __ldg(x4 + k4);
        float xs[4] = {xv.x, xv.y, xv.z, xv.w};
#pragma unroll
        for (int kk = 0; kk < 4; kk++) {
            float xk = xs[kk];
            if (LRELU) xk = xk > 0.0f ? xk : 0.01f * xk;
            const float4* Wr = (const float4*)&Ws[(k4 * 4 + kk) * FDIM];
#pragma unroll
            for (int j = 0; j < FDIM / 4; j++) {
                float4 w = Wr[j];
                a[4 * j + 0] = fmaf(xk, w.x, a[4 * j + 0]);
                a[4 * j + 1] = fmaf(xk, w.y, a[4 * j + 1]);
                a[4 * j + 2] = fmaf(xk, w.z, a[4 * j + 2]);
                a[4 * j + 3] = fmaf(xk, w.w, a[4 * j + 3]);
            }
        }
    }

    float di = g_dinv[r];
    float sn = di * di;
    float4* hr = (float4*)(h + (size_t)r * FDIM);
    float4* ar = (float4*)(acc + (size_t)r * FDIM);
#pragma unroll
    for (int j = 0; j < FDIM / 4; j++) {
        float4 hv = make_float4(a[4 * j], a[4 * j + 1], a[4 * j + 2], a[4 * j + 3]);
        hr[j] = hv;
        float4 ov;
        ov.x = fmaf(hv.x, sn, bs[4 * j + 0]);
        ov.y = fmaf(hv.y, sn, bs[4 * j + 1]);
        ov.z = fmaf(hv.z, sn, bs[4 * j + 2]);
        ov.w = fmaf(hv.w, sn, bs[4 * j + 3]);
        ar[j] = ov;
    }
}

// --- edge scatter: 16 threads per edge, each does one float4 gather + v4 RED
__global__ void __launch_bounds__(256)
k_scatter(const float* __restrict__ h, float* __restrict__ acc,
          const void* __restrict__ e, long long E) {
    long long idx = (long long)blockIdx.x * blockDim.x + threadIdx.x;
    long long ed = idx >> 4;
    if (ed >= E) return;
    int c = (int)(idx & 15) << 2;

    int s, d;
    if (g_is64) {
        const long long* p = (const long long*)e;
        s = (int)p[ed];
        d = (int)p[E + ed];
    } else {
        const int* p = (const int*)e;
        s = p[ed];
        d = p[E + ed];
    }
    float nrm = g_dinv[s] * g_dinv[d];
    float4 v = __ldg((const float4*)(h + (size_t)s * FDIM + c));
    v.x *= nrm; v.y *= nrm; v.z *= nrm; v.w *= nrm;
    float* dst = acc + (size_t)d * FDIM + c;
    asm volatile("red.global.add.v4.f32 [%0], {%1,%2,%3,%4};"
                 :: "l"(dst), "f"(v.x), "f"(v.y), "f"(v.z), "f"(v.w)
                 : "memory");
}

extern "C" void kernel_launch(void* const* d_in, const int* in_sizes, int n_in,
                              void* d_out, int out_size) {
    const float* x  = (const float*)d_in[0];
    const void*  ei = d_in[1];
    const float* W1 = (const float*)d_in[2];
    const float* b1 = (const float*)d_in[3];
    const float* W2 = (const float*)d_in[4];
    const float* b2 = (const float*)d_in[5];
    const float* W3 = (const float*)d_in[6];
    const float* b3 = (const float*)d_in[7];
    float* out = (float*)d_out;

    int n = in_sizes[0] / FDIM;
    long long E = (long long)in_sizes[1] / 2;

    float *hbuf, *accbuf;
    cudaGetSymbolAddress((void**)&hbuf, g_h);
    cudaGetSymbolAddress((void**)&accbuf, g_acc);

    int nb_n  = (n + 255) / 256;
    int nb_e  = (int)((E + 255) / 256);
    int nb_g  = (n + 127) / 128;
    long long sc_total = E * 16;
    int nb_sc = (int)((sc_total + 255) / 256);

    k_detect<<<1, 256>>>((const unsigned int*)ei, 2 * E);
    k_initdeg<<<nb_n, 256>>>(n);
    k_deg<<<nb_e, 256>>>(ei, E);
    k_dinv<<<nb_n, 256>>>(n);

    // layer 1
    k_gemm_init<0><<<nb_g, 128>>>(x, W1, b1, hbuf, accbuf, n);
    k_scatter<<<nb_sc, 256>>>(hbuf, accbuf, ei, E);
    // layer 2 (lrelu fused into GEMM input load; in-place acc is safe)
    k_gemm_init<1><<<nb_g, 128>>>(accbuf, W2, b2, hbuf, accbuf, n);
    k_scatter<<<nb_sc, 256>>>(hbuf, accbuf, ei, E);
    // layer 3 -> d_out (every element initialized by gemm_init)
    k_gemm_init<1><<<nb_g, 128>>>(accbuf, W3, b3, hbuf, out, n);
    k_scatter<<<nb_sc, 256>>>(hbuf, out, ei, E);
}

// round 4
// speedup vs baseline: 1.4534x; 1.4534x over previous
#include <cuda_runtime.h>
#include <cuda_bf16.h>
#include <cstdint>

// ---------------------------------------------------------------------------
// SimpleGCN on B200: CSR-based aggregation (no float atomics in hot path).
//   prep (once per launch): detect idx dtype, in-degree histogram, dinv,
//       exclusive scan -> row offsets, cursor-fill CSR {src, norm} per edge.
//   per layer: h = act(in) @ W   (thread-per-row GEMM, W in smem)
//              out[i] = sum_{e in CSR[i]} h[src_e]*norm_e + h[i]*dinv[i]^2 + b
// (Third submission of the CSR kernel: rounds 2 and 3 failed on container
//  acquisition, not on the kernel. One variable per round — no stacked edits.)
// ---------------------------------------------------------------------------

#define MAXN (1 << 17)   // >= 100000 nodes
#define MAXE (1 << 21)   // >= 1.6M edges
#define FDIM 64

__device__ float g_h[(size_t)MAXN * FDIM];    // transformed features
__device__ float g_acc[(size_t)MAXN * FDIM];  // layer outputs (intermediate)
__device__ float g_dinv[MAXN];
__device__ int   g_cnt[MAXN];                 // in-degree counts (CSR seg len)
__device__ int   g_row[MAXN];                 // CSR row starts (exclusive scan)
__device__ int   g_cur[MAXN];                 // fill cursors
__device__ int   g_bsum[256];                 // scan block sums
__device__ int2  g_edata[MAXE];               // {src, bitcast(norm)} sorted by dst
__device__ int   g_is64;

// --- dtype detection: int64 LE with small values has zero odd 32-bit words
__global__ void k_detect(const unsigned int* __restrict__ w, long long nwords) {
    __shared__ int cnt;
    if (threadIdx.x == 0) cnt = 0;
    __syncthreads();
    int zeros = 0;
    for (long long i = threadIdx.x; i < 2048 && i < nwords; i += blockDim.x)
        if ((i & 1) && w[i] == 0u) zeros++;
    atomicAdd(&cnt, zeros);
    __syncthreads();
    if (threadIdx.x == 0) g_is64 = (cnt > 512) ? 1 : 0;
}

__device__ __forceinline__ int load_idx(const void* e, long long pos) {
    if (g_is64) return (int)((const long long*)e)[pos];
    return ((const int*)e)[pos];
}

__global__ void k_zero2(int n) {
    int i = blockIdx.x * blockDim.x + threadIdx.x;
    if (i < n) { g_cnt[i] = 0; g_cur[i] = 0; }
}

__global__ void k_deg(const void* __restrict__ e, long long E) {
    long long i = (long long)blockIdx.x * blockDim.x + threadIdx.x;
    if (i >= E) return;
    atomicAdd(&g_cnt[load_idx(e, E + i)], 1);
}

__global__ void k_dinv(int n) {
    int i = blockIdx.x * blockDim.x + threadIdx.x;
    if (i < n) g_dinv[i] = rsqrtf((float)(1 + g_cnt[i]));  // +1 self loop
}

// --- exclusive scan of g_cnt -> g_row (3 kernels, blocks of 1024)
__global__ void k_scan1(int n) {
    __shared__ int sh[1024];
    int i = blockIdx.x * 1024 + threadIdx.x;
    int v = (i < n) ? g_cnt[i] : 0;
    sh[threadIdx.x] = v;
    __syncthreads();
#pragma unroll
    for (int off = 1; off < 1024; off <<= 1) {
        int t = (threadIdx.x >= off) ? sh[threadIdx.x - off] : 0;
        __syncthreads();
        sh[threadIdx.x] += t;
        __syncthreads();
    }
    if (i < n) g_row[i] = sh[threadIdx.x] - v;
    if (threadIdx.x == 1023) g_bsum[blockIdx.x] = sh[1023];
}

__global__ void k_scan2(int nb) {
    __shared__ int sh[256];
    int v = (threadIdx.x < nb) ? g_bsum[threadIdx.x] : 0;
    sh[threadIdx.x] = v;
    __syncthreads();
#pragma unroll
    for (int off = 1; off < 256; off <<= 1) {
        int t = (threadIdx.x >= off) ? sh[threadIdx.x - off] : 0;
        __syncthreads();
        sh[threadIdx.x] += t;
        __syncthreads();
    }
    if (threadIdx.x < nb) g_bsum[threadIdx.x] = sh[threadIdx.x] - v;  // exclusive
}

__global__ void k_scan3(int n) {
    int i = blockIdx.x * 1024 + threadIdx.x;
    if (i < n) g_row[i] += g_bsum[blockIdx.x];
}

// --- CSR fill: slot = row[dst] + cursor++ ; payload = {src, dinv[s]*dinv[d]}
__global__ void k_fill(const void* __restrict__ e, long long E) {
    long long i = (long long)blockIdx.x * blockDim.x + threadIdx.x;
    if (i >= E) return;
    int s, d;
    if (g_is64) {
        const long long* p = (const long long*)e;
        s = (int)p[i]; d = (int)p[E + i];
    } else {
        const int* p = (const int*)e;
        s = p[i]; d = p[E + i];
    }
    int pos = g_row[d] + atomicAdd(&g_cur[d], 1);
    g_edata[pos] = make_int2(s, __float_as_int(g_dinv[s] * g_dinv[d]));
}

// --- GEMM: h = act(in) @ W  (one thread per row, W staged in smem)
template <int LRELU>
__global__ void __launch_bounds__(128)
k_gemm(const float* __restrict__ in, const float* __restrict__ W,
       float* __restrict__ h, int n) {
    __shared__ float Ws[FDIM * FDIM];
    for (int i = threadIdx.x; i < FDIM * FDIM; i += blockDim.x) Ws[i] = W[i];
    __syncthreads();

    int r = blockIdx.x * blockDim.x + threadIdx.x;
    if (r >= n) return;

    float a[FDIM];
#pragma unroll
    for (int j = 0; j < FDIM; j++) a[j] = 0.0f;

    const float4* x4 = (const float4*)(in + (size_t)r * FDIM);
#pragma unroll 4
    for (int k4 = 0; k4 < FDIM / 4; k4++) {
        float4 xv = __ldg(x4 + k4);
        float xs[4] = {xv.x, xv.y, xv.z, xv.w};
#pragma unroll
        for (int kk = 0; kk < 4; kk++) {
            float xk = xs[kk];
            if (LRELU) xk = xk > 0.0f ? xk : 0.01f * xk;
            const float4* Wr = (const float4*)&Ws[(k4 * 4 + kk) * FDIM];
#pragma unroll
            for (int j = 0; j < FDIM / 4; j++) {
                float4 w = Wr[j];
                a[4 * j + 0] = fmaf(xk, w.x, a[4 * j + 0]);
                a[4 * j + 1] = fmaf(xk, w.y, a[4 * j + 1]);
                a[4 * j + 2] = fmaf(xk, w.z, a[4 * j + 2]);
                a[4 * j + 3] = fmaf(xk, w.w, a[4 * j + 3]);
            }
        }
    }

    float4* hr = (float4*)(h + (size_t)r * FDIM);
#pragma unroll
    for (int j = 0; j < FDIM / 4; j++)
        hr[j] = make_float4(a[4 * j], a[4 * j + 1], a[4 * j + 2], a[4 * j + 3]);
}

// --- CSR gather: 16 threads per node, each owns a float4 column slab.
//     out[i] = sum_e h[src_e]*norm_e + h[i]*dinv[i]^2 + b
__global__ void __launch_bounds__(256)
k_gather(const float* __restrict__ h, float* __restrict__ out,
         const float* __restrict__ b, int n) {
    int node = blockIdx.x * 16 + (threadIdx.x >> 4);
    if (node >= n) return;
    int c = (threadIdx.x & 15) << 2;

    const float4* h4 = (const float4*)h;
    int start = g_row[node];
    int deg   = g_cnt[node];
    float di  = g_dinv[node];
    float sn  = di * di;

    float4 self = h4[node * 16 + (c >> 2)];
    float4 bv   = __ldg((const float4*)(b + c));
    float4 a;
    a.x = fmaf(self.x, sn, bv.x);
    a.y = fmaf(self.y, sn, bv.y);
    a.z = fmaf(self.z, sn, bv.z);
    a.w = fmaf(self.w, sn, bv.w);

    const int2* ed = g_edata + start;
    int e = 0;
    for (; e + 4 <= deg; e += 4) {
        int2 e0 = ed[e], e1 = ed[e + 1], e2 = ed[e + 2], e3 = ed[e + 3];
        float4 v0 = h4[e0.x * 16 + (c >> 2)];
        float4 v1 = h4[e1.x * 16 + (c >> 2)];
        float4 v2 = h4[e2.x * 16 + (c >> 2)];
        float4 v3 = h4[e3.x * 16 + (c >> 2)];
        float n0 = __int_as_float(e0.y), n1 = __int_as_float(e1.y);
        float n2 = __int_as_float(e2.y), n3 = __int_as_float(e3.y);
        a.x = fmaf(v0.x, n0, a.x); a.y = fmaf(v0.y, n0, a.y);
        a.z = fmaf(v0.z, n0, a.z); a.w = fmaf(v0.w, n0, a.w);
        a.x = fmaf(v1.x, n1, a.x); a.y = fmaf(v1.y, n1, a.y);
        a.z = fmaf(v1.z, n1, a.z); a.w = fmaf(v1.w, n1, a.w);
        a.x = fmaf(v2.x, n2, a.x); a.y = fmaf(v2.y, n2, a.y);
        a.z = fmaf(v2.z, n2, a.z); a.w = fmaf(v2.w, n2, a.w);
        a.x = fmaf(v3.x, n3, a.x); a.y = fmaf(v3.y, n3, a.y);
        a.z = fmaf(v3.z, n3, a.z); a.w = fmaf(v3.w, n3, a.w);
    }
    for (; e < deg; e++) {
        int2 ee = ed[e];
        float4 v = h4[ee.x * 16 + (c >> 2)];
        float nn = __int_as_float(ee.y);
        a.x = fmaf(v.x, nn, a.x); a.y = fmaf(v.y, nn, a.y);
        a.z = fmaf(v.z, nn, a.z); a.w = fmaf(v.w, nn, a.w);
    }

    ((float4*)out)[node * 16 + (c >> 2)] = a;
}

extern "C" void kernel_launch(void* const* d_in, const int* in_sizes, int n_in,
                              void* d_out, int out_size) {
    const float* x  = (const float*)d_in[0];
    const void*  ei = d_in[1];
    const float* W1 = (const float*)d_in[2];
    const float* b1 = (const float*)d_in[3];
    const float* W2 = (const float*)d_in[4];
    const float* b2 = (const float*)d_in[5];
    const float* W3 = (const float*)d_in[6];
    const float* b3 = (const float*)d_in[7];
    float* out = (float*)d_out;

    int n = in_sizes[0] / FDIM;
    long long E = (long long)in_sizes[1] / 2;

    float *hbuf, *accbuf;
    cudaGetSymbolAddress((void**)&hbuf, g_h);
    cudaGetSymbolAddress((void**)&accbuf, g_acc);

    int nb_n    = (n + 255) / 256;
    int nb_e    = (int)((E + 255) / 256);
    int nb_g    = (n + 127) / 128;
    int nb_scan = (n + 1023) / 1024;
    int nb_ga   = (n + 15) / 16;

    // --- prep: CSR build
    k_detect<<<1, 256>>>((const unsigned int*)ei, 2 * E);
    k_zero2<<<nb_n, 256>>>(n);
    k_deg<<<nb_e, 256>>>(ei, E);
    k_dinv<<<nb_n, 256>>>(n);
    k_scan1<<<nb_scan, 1024>>>(n);
    k_scan2<<<1, 256>>>(nb_scan);
    k_scan3<<<nb_scan, 1024>>>(n);
    k_fill<<<nb_e, 256>>>(ei, E);

    // --- layer 1
    k_gemm<0><<<nb_g, 128>>>(x, W1, hbuf, n);
    k_gather<<<nb_ga, 256>>>(hbuf, accbuf, b1, n);
    // --- layer 2
    k_gemm<1><<<nb_g, 128>>>(accbuf, W2, hbuf, n);
    k_gather<<<nb_ga, 256>>>(hbuf, accbuf, b2, n);
    // --- layer 3
    k_gemm<1><<<nb_g, 128>>>(accbuf, W3, hbuf, n);
    k_gather<<<nb_ga, 256>>>(hbuf, out, b3, n);
}